// round 3
// baseline (speedup 1.0000x reference)
#include <cuda_runtime.h>

// GLCM entropy per image, pooled over 4 angles (d=1, wraparound), 16 levels.
// x: [N_IMG, 512, 512] f32 in [0,1). out: each image slice filled with its scalar entropy.

#define HH 512
#define WW 512
#define RPB 16         // rows per histogram block
#define TPB 256
#define MAXIMG 256

__device__ unsigned int g_counts[MAXIMG * 256];
__device__ float g_ent[MAXIMG];

__global__ void zero_counts_kernel(int n) {
    int i = blockIdx.x * blockDim.x + threadIdx.x;
    if (i < n) g_counts[i] = 0u;
}

__global__ __launch_bounds__(TPB) void hist_kernel(const float* __restrict__ x) {
    const int img = blockIdx.y;
    const int r0 = blockIdx.x * RPB;
    const float4* base4 = (const float4*)(x + (size_t)img * (HH * WW));

    __shared__ unsigned char tile[(RPB + 1) * WW];   // rows r0-1 .. r0+RPB-1 (quantized)
    __shared__ unsigned int hist[8 * 256];           // per-warp histograms

    const int tid = threadIdx.x;

    #pragma unroll
    for (int k = tid; k < 8 * 256; k += TPB) hist[k] = 0u;

    // Load + quantize tile (vectorized: 128 float4 per row).
    // tile row rr corresponds to image row (r0 - 1 + rr) mod H.
    const int W4 = WW / 4;                           // 128
    for (int k = tid; k < (RPB + 1) * W4; k += TPB) {
        int rr = k >> 7;                             // k / 128
        int c4 = k & (W4 - 1);
        int gr = (r0 - 1 + rr + HH) & (HH - 1);      // HH power of two
        float4 v = base4[gr * W4 + c4];
        int o = rr * WW + c4 * 4;
        tile[o + 0] = (unsigned char)(int)(v.x * 15.0f);  // trunc == (x*(L-1)).astype(int)
        tile[o + 1] = (unsigned char)(int)(v.y * 15.0f);
        tile[o + 2] = (unsigned char)(int)(v.z * 15.0f);
        tile[o + 3] = (unsigned char)(int)(v.w * 15.0f);
    }
    __syncthreads();

    unsigned int* wh = hist + ((tid >> 5) << 8);     // this warp's private histogram

    // Each pixel (i,j) pairs with: left (angle 0), up-right (45), up (90), up-left (135).
    for (int p = tid; p < RPB * WW; p += TPB) {
        int rr = (p >> 9) + 1;                       // tile rows 1..RPB
        int col = p & (WW - 1);
        int row = rr * WW;
        int up  = row - WW;
        int jm = (col - 1) & (WW - 1);
        int jp = (col + 1) & (WW - 1);

        int qb = ((int)tile[row + col]) << 4;
        atomicAdd(&wh[qb + tile[row + jm]], 1u);     // angle 0
        atomicAdd(&wh[qb + tile[up  + jp]], 1u);     // angle 45
        atomicAdd(&wh[qb + tile[up  + col]], 1u);    // angle 90
        atomicAdd(&wh[qb + tile[up  + jm]], 1u);     // angle 135
    }
    __syncthreads();

    // Merge 8 warp histograms; one global atomic per bin per block.
    unsigned int s = 0;
    #pragma unroll
    for (int w = 0; w < 8; w++) s += hist[w * 256 + tid];
    atomicAdd(&g_counts[img * 256 + tid], s);
}

__global__ __launch_bounds__(256) void entropy_kernel() {
    const int img = blockIdx.x;
    const int tid = threadIdx.x;
    __shared__ float red[256];

    float c = (float)g_counts[img * 256 + tid];
    const float inv = 1.0f / (4.0f * HH * WW);       // counts.sum() == 4*H*W exactly
    float p = c * inv;
    red[tid] = p * logf(p + 1e-10f);
    __syncthreads();

    for (int s = 128; s > 0; s >>= 1) {
        if (tid < s) red[tid] += red[tid + s];
        __syncthreads();
    }
    if (tid == 0) g_ent[img] = -red[0];
}

__global__ void fill_kernel(float4* __restrict__ out, int n4) {
    int i = blockIdx.x * blockDim.x + threadIdx.x;
    if (i < n4) {
        // H*W = 2^18 floats per image -> 2^16 float4 per image
        float v = g_ent[i >> 16];
        out[i] = make_float4(v, v, v, v);
    }
}

extern "C" void kernel_launch(void* const* d_in, const int* in_sizes, int n_in,
                              void* d_out, int out_size) {
    const float* x = (const float*)d_in[0];
    int n_img = in_sizes[0] / (HH * WW);             // 8*16 = 128

    int nc = n_img * 256;
    zero_counts_kernel<<<(nc + 255) / 256, 256>>>(nc);

    dim3 hgrid(HH / RPB, n_img);
    hist_kernel<<<hgrid, TPB>>>(x);

    entropy_kernel<<<n_img, 256>>>();

    int n4 = out_size / 4;
    fill_kernel<<<(n4 + 255) / 256, 256>>>((float4*)d_out, n4);
}

// round 4
// speedup vs baseline: 1.0670x; 1.0670x over previous
#include <cuda_runtime.h>

// GLCM entropy per image, pooled over 4 angles (d=1, wraparound), 16 levels.
// x: [N_IMG, 512, 512] f32 in [0,1). out: each (b,c) slice filled with its scalar entropy.

#define HH 512
#define WW 512
#define RPB 16         // rows per histogram block
#define TPB 256
#define MAXIMG 256

__device__ unsigned int g_counts[MAXIMG * 256];
__device__ float g_ent[MAXIMG];

__global__ void zero_counts_kernel(int n) {
    int i = blockIdx.x * blockDim.x + threadIdx.x;
    if (i < n) g_counts[i] = 0u;
}

__global__ __launch_bounds__(TPB) void hist_kernel(const float* __restrict__ x) {
    const int img = blockIdx.y;
    const int r0 = blockIdx.x * RPB;
    const float4* base4 = (const float4*)(x + (size_t)img * (HH * WW));

    // Quantized tile stored as packed words: 128 uint32 per row (4 px/word),
    // rows r0-1 .. r0+RPB-1.
    __shared__ unsigned int tile32[(RPB + 1) * (WW / 4)];
    __shared__ unsigned int hist[8 * 256];           // per-warp histograms

    const int tid = threadIdx.x;
    const int W4 = WW / 4;                           // 128 words per row

    #pragma unroll
    for (int k = tid; k < 8 * 256; k += TPB) hist[k] = 0u;

    // Load + quantize, pack 4 bytes -> 1 word STS.
    for (int k = tid; k < (RPB + 1) * W4; k += TPB) {
        int rr = k >> 7;                             // k / 128
        int c4 = k & (W4 - 1);
        int gr = (r0 - 1 + rr + HH) & (HH - 1);
        float4 v = base4[gr * W4 + c4];
        unsigned int b0 = (unsigned int)(int)(v.x * 15.0f);   // trunc == (x*15).astype(int)
        unsigned int b1 = (unsigned int)(int)(v.y * 15.0f);
        unsigned int b2 = (unsigned int)(int)(v.z * 15.0f);
        unsigned int b3 = (unsigned int)(int)(v.w * 15.0f);
        tile32[k] = b0 | (b1 << 8) | (b2 << 16) | (b3 << 24);
    }
    __syncthreads();

    unsigned int* wh = hist + ((tid >> 5) << 8);     // this warp's private histogram

    // Each thread processes one aligned word = 4 pixels per iter.
    // Pixel (i,j) pairs with: left (0deg), up-right (45), up (90), up-left (135).
    for (int w = tid; w < RPB * W4; w += TPB) {
        int rr = (w >> 7) + 1;                       // tile rows 1..RPB
        int c4 = w & (W4 - 1);
        int row = rr * W4;
        int up  = row - W4;
        int c4m = (c4 - 1) & (W4 - 1);
        int c4p = (c4 + 1) & (W4 - 1);

        unsigned int cw  = tile32[row + c4];
        unsigned int uw  = tile32[up + c4];
        unsigned int lb  = tile32[row + c4m] >> 24;  // left neighbor of pixel 0
        unsigned int ulb = tile32[up + c4m] >> 24;   // up-left of pixel 0
        unsigned int urb = tile32[up + c4p] & 0xFFu; // up-right of pixel 3

        unsigned int cl = (cw << 8) | lb;            // byte k = left  neighbor of pixel k
        unsigned int ul = (uw << 8) | ulb;           // byte k = up-left
        unsigned int ur = (uw >> 8) | (urb << 24);   // byte k = up-right
                                                     // byte k of uw = up neighbor
        #pragma unroll
        for (int k = 0; k < 4; k++) {
            int sh = k * 8;
            unsigned int qb = ((cw >> sh) & 15u) << 4;
            atomicAdd(&wh[qb + ((cl >> sh) & 15u)], 1u);   // 0 deg
            atomicAdd(&wh[qb + ((ur >> sh) & 15u)], 1u);   // 45 deg
            atomicAdd(&wh[qb + ((uw >> sh) & 15u)], 1u);   // 90 deg
            atomicAdd(&wh[qb + ((ul >> sh) & 15u)], 1u);   // 135 deg
        }
    }
    __syncthreads();

    // Merge 8 warp histograms; one global atomic per bin per block.
    unsigned int s = 0;
    #pragma unroll
    for (int w = 0; w < 8; w++) s += hist[w * 256 + tid];
    atomicAdd(&g_counts[img * 256 + tid], s);
}

__global__ __launch_bounds__(256) void entropy_kernel() {
    const int img = blockIdx.x;
    const int tid = threadIdx.x;
    __shared__ float warp_red[8];

    float c = (float)g_counts[img * 256 + tid];
    const float inv = 1.0f / (4.0f * HH * WW);       // counts.sum() == 4*H*W exactly
    float p = c * inv;
    float v = p * __logf(p + 1e-10f);

    #pragma unroll
    for (int s = 16; s > 0; s >>= 1) v += __shfl_xor_sync(0xFFFFFFFFu, v, s);
    if ((tid & 31) == 0) warp_red[tid >> 5] = v;
    __syncthreads();
    if (tid < 8) {
        float t = warp_red[tid];
        #pragma unroll
        for (int s = 4; s > 0; s >>= 1) t += __shfl_xor_sync(0xFFu, t, s);
        if (tid == 0) g_ent[img] = -t;
    }
}

__global__ __launch_bounds__(256) void fill_kernel(float4* __restrict__ out, int n4) {
    // Each thread writes 4 float4 (64B). Per-image region = 2^16 float4.
    int base = blockIdx.x * (256 * 4) + threadIdx.x;
    #pragma unroll
    for (int i = 0; i < 4; i++) {
        int idx = base + i * 256;
        if (idx < n4) {
            float v = g_ent[idx >> 16];
            __stcs(&out[idx], make_float4(v, v, v, v));
        }
    }
}

extern "C" void kernel_launch(void* const* d_in, const int* in_sizes, int n_in,
                              void* d_out, int out_size) {
    const float* x = (const float*)d_in[0];
    int n_img = in_sizes[0] / (HH * WW);             // 8*16 = 128

    int nc = n_img * 256;
    zero_counts_kernel<<<(nc + 255) / 256, 256>>>(nc);

    dim3 hgrid(HH / RPB, n_img);
    hist_kernel<<<hgrid, TPB>>>(x);

    entropy_kernel<<<n_img, 256>>>();

    int n4 = out_size / 4;
    fill_kernel<<<(n4 + 256 * 4 - 1) / (256 * 4), 256>>>((float4*)d_out, n4);
}

// round 8
// speedup vs baseline: 1.0778x; 1.0101x over previous
#include <cuda_runtime.h>

// GLCM entropy per image, pooled over 4 angles (d=1, wraparound), 16 levels.
// x: [N_IMG, 512, 512] f32 in [0,1). out: each (b,c) slice filled with its scalar entropy.

#define HH 512
#define WW 512
#define RPB 16         // rows per histogram block
#define TPB 256
#define MAXIMG 256

__device__ unsigned int g_counts[MAXIMG * 256];
__device__ float g_ent[MAXIMG];

__global__ void zero_counts_kernel(int n) {
    int i = blockIdx.x * blockDim.x + threadIdx.x;
    if (i < n) g_counts[i] = 0u;
}

__global__ __launch_bounds__(TPB) void hist_kernel(const float* __restrict__ x) {
    const int img = blockIdx.y;
    const int r0 = blockIdx.x * RPB;
    const float4* base4 = (const float4*)(x + (size_t)img * (HH * WW));

    // Quantized tile as packed words: 128 uint32 per row (4 px/word), rows r0-1..r0+RPB-1.
    __shared__ unsigned int tile32[(RPB + 1) * (WW / 4)];
    __shared__ unsigned int hist[8 * 256];           // per-warp histograms

    const int tid = threadIdx.x;
    const int W4 = WW / 4;                           // 128 words per row

    #pragma unroll
    for (int k = tid; k < 8 * 256; k += TPB) hist[k] = 0u;

    // Load + quantize, pack 4 bytes -> 1 word STS.
    for (int k = tid; k < (RPB + 1) * W4; k += TPB) {
        int rr = k >> 7;                             // k / 128
        int c4 = k & (W4 - 1);
        int gr = (r0 - 1 + rr + HH) & (HH - 1);
        float4 v = base4[gr * W4 + c4];
        unsigned int b0 = (unsigned int)(int)(v.x * 15.0f);   // trunc == (x*15).astype(int)
        unsigned int b1 = (unsigned int)(int)(v.y * 15.0f);
        unsigned int b2 = (unsigned int)(int)(v.z * 15.0f);
        unsigned int b3 = (unsigned int)(int)(v.w * 15.0f);
        tile32[k] = b0 | (b1 << 8) | (b2 << 16) | (b3 << 24);
    }
    __syncthreads();

    unsigned int* wh = hist + ((tid >> 5) << 8);     // this warp's private histogram

    // Each thread: one aligned word = 4 pixels.
    // Pixel pairs with: left (0deg), up-right (45), up (90), up-left (135).
    for (int w = tid; w < RPB * W4; w += TPB) {
        int rr = (w >> 7) + 1;                       // tile rows 1..RPB
        int c4 = w & (W4 - 1);
        int row = rr * W4;
        int up  = row - W4;
        int c4m = (c4 - 1) & (W4 - 1);
        int c4p = (c4 + 1) & (W4 - 1);

        unsigned int cw  = tile32[row + c4];
        unsigned int uw  = tile32[up + c4];
        unsigned int lb  = tile32[row + c4m] >> 24;  // left neighbor of pixel 0
        unsigned int ulb = tile32[up + c4m] >> 24;   // up-left of pixel 0
        unsigned int urb = tile32[up + c4p] & 0xFFu; // up-right of pixel 3

        unsigned int cl = (cw << 8) | lb;            // byte k = left  neighbor of pixel k
        unsigned int ul = (uw << 8) | ulb;           // byte k = up-left
        unsigned int ur = (uw >> 8) | (urb << 24);   // byte k = up-right
                                                     // byte k of uw = up neighbor

        // Per-byte bin indices: bin = (q<<4) | s, computed 4-at-a-time per angle.
        unsigned int qb   = (cw << 4) & 0xF0F0F0F0u;
        unsigned int b0   = qb | cl;
        unsigned int b45  = qb | ur;
        unsigned int b90  = qb | uw;
        unsigned int b135 = qb | ul;

        #pragma unroll
        for (int k = 0; k < 4; k++) {
            int sh = k * 8;
            atomicAdd(&wh[(b0   >> sh) & 255u], 1u);
            atomicAdd(&wh[(b45  >> sh) & 255u], 1u);
            atomicAdd(&wh[(b90  >> sh) & 255u], 1u);
            atomicAdd(&wh[(b135 >> sh) & 255u], 1u);
        }
    }
    __syncthreads();

    // Merge 8 warp histograms; one global atomic per bin per block.
    unsigned int s = 0;
    #pragma unroll
    for (int w = 0; w < 8; w++) s += hist[w * 256 + tid];
    atomicAdd(&g_counts[img * 256 + tid], s);
}

__global__ __launch_bounds__(256) void entropy_kernel() {
    const int img = blockIdx.x;
    const int tid = threadIdx.x;
    __shared__ float warp_red[8];

    float c = (float)g_counts[img * 256 + tid];
    const float inv = 1.0f / (4.0f * HH * WW);       // counts.sum() == 4*H*W exactly
    float p = c * inv;
    float v = p * __logf(p + 1e-10f);

    #pragma unroll
    for (int s = 16; s > 0; s >>= 1) v += __shfl_xor_sync(0xFFFFFFFFu, v, s);
    if ((tid & 31) == 0) warp_red[tid >> 5] = v;
    __syncthreads();
    if (tid < 8) {
        float t = warp_red[tid];
        #pragma unroll
        for (int s = 4; s > 0; s >>= 1) t += __shfl_xor_sync(0xFFu, t, s);
        if (tid == 0) g_ent[img] = -t;
    }
}

__global__ __launch_bounds__(256) void fill_kernel(float4* __restrict__ out, int n4) {
    // Each thread writes 8 float4 (128B), lane-contiguous per step (512B/warp).
    int base = blockIdx.x * (256 * 8) + threadIdx.x;
    #pragma unroll
    for (int i = 0; i < 8; i++) {
        int idx = base + i * 256;
        if (idx < n4) {
            float v = g_ent[idx >> 16];              // 2^16 float4 per image
            __stcs(&out[idx], make_float4(v, v, v, v));
        }
    }
}

extern "C" void kernel_launch(void* const* d_in, const int* in_sizes, int n_in,
                              void* d_out, int out_size) {
    const float* x = (const float*)d_in[0];
    int n_img = in_sizes[0] / (HH * WW);             // 8*16 = 128

    int nc = n_img * 256;
    zero_counts_kernel<<<(nc + 255) / 256, 256>>>(nc);

    dim3 hgrid(HH / RPB, n_img);
    hist_kernel<<<hgrid, TPB>>>(x);

    entropy_kernel<<<n_img, 256>>>();

    int n4 = out_size / 4;
    fill_kernel<<<(n4 + 256 * 8 - 1) / (256 * 8), 256>>>((float4*)d_out, n4);
}